// round 16
// baseline (speedup 1.0000x reference)
#include <cuda_runtime.h>
#include <cstdint>
#include <math.h>

#define EMB    64
#define NS     25
#define DEG    64
#define BATCH  4096
#define NSAMP  (BATCH * NS)
#define FR     68                     // shared feat row stride (conflict-free)
#define CGRID  148                    // compute blocks per chunk (1/SM)
#define NCHK   4
#define CHUNKB (BATCH / NCHK)         // 1024 batches per chunk

typedef unsigned long long ull;

// fma.rn.f32x2 — packed fp32 FMA (Blackwell). acc += a*b (two lanes)
#define FFMA2(acc, a, b) \
    asm("fma.rn.f32x2 %0, %1, %2, %3;" : "=l"(acc) : "l"(a), "l"(b), "l"(acc))

#define CVT_TF32(u, f) \
    asm("cvt.rna.tf32.f32 %0, %1;" : "=r"(u) : "f"(f))

#define MMA_TF32(c0, c1, c2, c3, a0, a1, a2, a3, b0, b1)                     \
    asm("mma.sync.aligned.m16n8k8.row.col.f32.tf32.tf32.f32 "                \
        "{%0,%1,%2,%3},{%4,%5,%6,%7},{%8,%9},{%0,%1,%2,%3};"                 \
        : "+f"(c0), "+f"(c1), "+f"(c2), "+f"(c3)                             \
        : "r"(a0), "r"(a1), "r"(a2), "r"(a3), "r"(b0), "r"(b1))

// ---------------- static device scratch (no allocation) --------------------
__device__ float g_Atc[256 * 64];             // folded layer-1 weights [c][k]
__device__ float g_bias1[256];                // [b1x ; b1n]
__device__ float g_x0[128];                   // feats0 @ w1x.T (pre-relu)
__device__ float g_W2t[512 * 256];            // layer-2 weights [128 kp][256 c][2]
__device__ float g_feats[(size_t)NSAMP * 128];// per sample: [e1(64)|mean2(64)]
__device__ float g_scr[(size_t)BATCH * 512];  // per batch: [h0cat(256)|h1mean(256)]

// ---------------------------------------------------------------------------
// prep_all: merged prep_A (blocks 0-31), prep_B (block 32), prep_W2 (33-544)
// ---------------------------------------------------------------------------
__global__ void __launch_bounds__(256)
prep_all(const float* __restrict__ emb,
         const float* __restrict__ prep_W,
         const float* __restrict__ prep_b,
         const float* __restrict__ w1x,
         const float* __restrict__ w1n,
         const float* __restrict__ w2x,
         const float* __restrict__ w2n,
         int n_nodes) {
    const int bid = blockIdx.x;
    const int t = threadIdx.x;

    if (bid < 32) {                   // ---- prep_A ----
        int idx = bid * 256 + t;      // 0..8191
        int k = idx >> 7, h = idx & 127;
        float ax = 0.f, an = 0.f;
#pragma unroll
        for (int c = 0; c < 64; c++) {
            float p = prep_W[c * 64 + k];
            ax += p * w1x[h * 64 + c];
            an += p * w1n[h * 64 + c];
        }
        g_Atc[h * 64 + k]         = ax;
        g_Atc[(128 + h) * 64 + k] = an;
    } else if (bid == 32) {           // ---- prep_B ----
        __shared__ float f0[64];
        if (t < 64) {
            const float* e = emb + (size_t)n_nodes * 64;
            float a = prep_b[t];
#pragma unroll
            for (int k = 0; k < 64; k++) a += e[k] * prep_W[t * 64 + k];
            f0[t] = a;
        }
        __syncthreads();
        if (t < 128) {
            float x0 = 0.f, bx = 0.f, bn = 0.f;
#pragma unroll
            for (int c = 0; c < 64; c++) {
                x0 += f0[c]     * w1x[t * 64 + c];
                bx += prep_b[c] * w1x[t * 64 + c];
                bn += prep_b[c] * w1n[t * 64 + c];
            }
            g_x0[t]          = x0;
            g_bias1[t]       = bx;
            g_bias1[128 + t] = bn;
        }
    } else {                          // ---- prep_W2 ----
        int idx = (bid - 33) * 256 + t;   // 0..131071
        int c = idx & 255, kk = idx >> 8;
        float v = (c < 128) ? w2x[c * 256 + kk] : w2n[(c - 128) * 256 + kk];
        g_W2t[(kk >> 1) * 512 + c * 2 + (kk & 1)] = v;
    }
}

// ---------------------------------------------------------------------------
// gather_kernel: 1 warp = 1 sample (HBM-roofline proven), chunked via sBase.
// ---------------------------------------------------------------------------
__global__ void __launch_bounds__(256)
gather_kernel(const float* __restrict__ emb,
              const int* __restrict__ ids,
              const int* __restrict__ adj,
              const int* __restrict__ perm1,
              const int* __restrict__ perm2,
              int sBase) {
    int t = threadIdx.x;
    int w = t >> 5, lane = t & 31;
    int s = sBase + blockIdx.x * 8 + w;          // sample index
    int i = s / NS;
    int j = s - i * NS;

    int id0 = __ldg(&ids[i]);
    int p1  = __ldg(&perm1[j]);
    int id1 = __ldg(&adj[(size_t)id0 * DEG + p1]);

    int p2  = __ldg(&perm2[lane < NS ? lane : 0]);
    int nb  = __ldg(&adj[(size_t)id1 * DEG + p2]);

    float2 e1 = *(const float2*)(emb + (size_t)id1 * 64 + 2 * lane);

    float sx = 0.f, sy = 0.f;
#pragma unroll
    for (int k = 0; k < NS; k++) {
        int idk = __shfl_sync(0xffffffffu, nb, k);
        float2 v = *(const float2*)(emb + (size_t)idk * 64 + 2 * lane);
        sx += v.x; sy += v.y;
    }
    const float inv25 = 1.0f / 25.0f;
    float* dst = g_feats + (size_t)s * 128;
    *(float2*)(dst + 2 * lane)      = e1;
    *(float2*)(dst + 64 + 2 * lane) = make_float2(sx * inv25, sy * inv25);
}

// ---------------------------------------------------------------------------
// compute_mma: tf32 mma.sync compute (proven), chunked: 148 blocks process
// batches [iBase, iBase+CHUNKB) grid-stride with cp.async double buffering.
// ---------------------------------------------------------------------------
__device__ __forceinline__ void cp16(unsigned int saddr, const void* g) {
    asm volatile("cp.async.cg.shared.global [%0], [%1], 16;" :: "r"(saddr), "l"(g));
}

__global__ void __launch_bounds__(256, 2)
compute_mma(int iBase) {
    __shared__ float Fbuf[2][2][32 * FR];     // [buf][x/n][rows]

    const int t = threadIdx.x;
    const int w = t >> 5, lane = t & 31;
    const int g = lane >> 2, t4 = lane & 3;
    const int wcol = w * 32;                  // global output col base
    const bool isN = (w >= 4);
    const float inv25 = 1.0f / 25.0f;

    // ---- load B fragments (weights) once: b[n8][k8][2] ----
    unsigned bfr[4][8][2];
#pragma unroll
    for (int n8 = 0; n8 < 4; n8++) {
        int c = wcol + n8 * 8 + g;
#pragma unroll
        for (int k8 = 0; k8 < 8; k8++) {
            float v0 = g_Atc[c * 64 + k8 * 8 + t4];
            float v1 = g_Atc[c * 64 + k8 * 8 + t4 + 4];
            CVT_TF32(bfr[n8][k8][0], v0);
            CVT_TF32(bfr[n8][k8][1], v1);
        }
    }
    float biasE[4], biasO[4];
#pragma unroll
    for (int n8 = 0; n8 < 4; n8++) {
        biasE[n8] = g_bias1[wcol + n8 * 8 + 2 * t4];
        biasO[n8] = g_bias1[wcol + n8 * 8 + 2 * t4 + 1];
    }
    const float x0v = (t < 128) ? g_x0[t] : 0.f;

#define STAGE(i_, b_)                                                         \
    do {                                                                      \
        const float4* src_ = (const float4*)(g_feats + (size_t)(i_) * NS * 128); \
        unsigned bx_ = (unsigned)__cvta_generic_to_shared(&Fbuf[b_][0][0]);   \
        unsigned bn_ = (unsigned)__cvta_generic_to_shared(&Fbuf[b_][1][0]);   \
        _Pragma("unroll")                                                     \
        for (int idx = t; idx < 400; idx += 256) {                            \
            int s_ = idx >> 4, q_ = idx & 15;                                 \
            cp16(bx_ + (s_ * FR + q_ * 4) * 4, src_ + s_ * 32 + q_);          \
            cp16(bn_ + (s_ * FR + q_ * 4) * 4, src_ + s_ * 32 + 16 + q_);     \
        }                                                                     \
        asm volatile("cp.async.commit_group;" ::: "memory");                  \
    } while (0)

    const int iEnd = iBase + CHUNKB;
    int i = iBase + blockIdx.x;
    if (i < iEnd) STAGE(i, 0);
    int buf = 0;

    for (; i < iEnd; i += CGRID) {
        const int nxt = i + CGRID;
        if (nxt < iEnd) {
            STAGE(nxt, buf ^ 1);
            asm volatile("cp.async.wait_group 1;" ::: "memory");
        } else {
            asm volatile("cp.async.wait_group 0;" ::: "memory");
        }
        __syncthreads();              // current buffer fully staged

        float* Fx = &Fbuf[buf][0][0];
        float* Fn = &Fbuf[buf][1][0];
        if (t < 64) {                 // mean1 -> Fn row 25
            float m = 0.f;
#pragma unroll
            for (int s = 0; s < NS; s++) m += Fx[s * FR + t];
            Fn[25 * FR + t] = m * inv25;
        }
        __syncthreads();

        const float* Fw = isN ? Fn : Fx;

        // ---- mma ----
        float cfr[2][4][4];
#pragma unroll
        for (int m = 0; m < 2; m++)
#pragma unroll
            for (int n8 = 0; n8 < 4; n8++)
#pragma unroll
                for (int q = 0; q < 4; q++) cfr[m][n8][q] = 0.f;

#pragma unroll
        for (int m = 0; m < 2; m++) {
            int rb = m * 16;
#pragma unroll
            for (int k8 = 0; k8 < 8; k8++) {
                unsigned a0, a1, a2, a3;
                CVT_TF32(a0, Fw[(rb + g) * FR + k8 * 8 + t4]);
                CVT_TF32(a1, Fw[(rb + g + 8) * FR + k8 * 8 + t4]);
                CVT_TF32(a2, Fw[(rb + g) * FR + k8 * 8 + t4 + 4]);
                CVT_TF32(a3, Fw[(rb + g + 8) * FR + k8 * 8 + t4 + 4]);
#pragma unroll
                for (int n8 = 0; n8 < 4; n8++)
                    MMA_TF32(cfr[m][n8][0], cfr[m][n8][1], cfr[m][n8][2], cfr[m][n8][3],
                             a0, a1, a2, a3, bfr[n8][k8][0], bfr[n8][k8][1]);
            }
        }

        // ---- epilogue ----
        float* scr = g_scr + (size_t)i * 512;
        if (t < 128) scr[t] = fmaxf(x0v, 0.f);     // h0 x-part
#pragma unroll
        for (int n8 = 0; n8 < 4; n8++) {
            float vE = fmaxf(cfr[0][n8][0] + biasE[n8], 0.f)
                     + fmaxf(cfr[0][n8][2] + biasE[n8], 0.f)
                     + fmaxf(cfr[1][n8][0] + biasE[n8], 0.f);
            float vO = fmaxf(cfr[0][n8][1] + biasO[n8], 0.f)
                     + fmaxf(cfr[0][n8][3] + biasO[n8], 0.f)
                     + fmaxf(cfr[1][n8][1] + biasO[n8], 0.f);
            if (g == 0) {
                vE += fmaxf(cfr[1][n8][2] + biasE[n8], 0.f);
                vO += fmaxf(cfr[1][n8][3] + biasO[n8], 0.f);
            }
            if (isN && g == 1) {       // row 25 = mean1 @ A1n -> h0 n-part
                scr[wcol + n8 * 8 + 2 * t4]     = fmaxf(cfr[1][n8][2] + biasE[n8], 0.f);
                scr[wcol + n8 * 8 + 2 * t4 + 1] = fmaxf(cfr[1][n8][3] + biasO[n8], 0.f);
            }
#pragma unroll
            for (int o = 4; o < 32; o <<= 1) {
                vE += __shfl_xor_sync(0xffffffffu, vE, o);
                vO += __shfl_xor_sync(0xffffffffu, vO, o);
            }
            if (lane < 4) {
                scr[256 + wcol + n8 * 8 + 2 * lane]     = vE * inv25;
                scr[256 + wcol + n8 * 8 + 2 * lane + 1] = vO * inv25;
            }
        }
        __syncthreads();              // everyone done with buf before refill
        buf ^= 1;
    }
#undef STAGE
}

// ---------------------------------------------------------------------------
// final2: layer-2 GEMM with packed transposed weights (proven), chunked.
// ---------------------------------------------------------------------------
__global__ void __launch_bounds__(256)
final2(const float* __restrict__ fcW,
       const float* __restrict__ fcb,
       float* __restrict__ out,
       int rowBase) {
    extern __shared__ float fsm[];
    float* in_sh = fsm;                 // 32 x 512
    float* sSq   = fsm + 32 * 512;
    float* sDot  = sSq + 32;

    int t  = threadIdx.x;
    int r0 = rowBase + blockIdx.x * 32;

    {
        const float4* src = (const float4*)(g_scr + (size_t)r0 * 512);
        float4* dst = (float4*)in_sh;
#pragma unroll
        for (int q = 0; q < 16; q++) dst[t + q * 256] = src[t + q * 256];
    }
    if (t < 32) { sSq[t] = 0.f; sDot[t] = 0.f; }
    __syncthreads();

    const int c4 = (t & 63) * 4;
    const int rg = t >> 6;
    const int ioff = (c4 < 128) ? 0 : 256;
    const float* xb = in_sh + rg * 8 * 512 + ioff;

    ull acc[8][4];
#pragma unroll
    for (int r = 0; r < 8; r++)
#pragma unroll
        for (int j = 0; j < 4; j++) acc[r][j] = 0ull;

#pragma unroll 4
    for (int kp = 0; kp < 128; kp++) {
        ulonglong2 wA = *(const ulonglong2*)(g_W2t + kp * 512 + c4 * 2);
        ulonglong2 wB = *(const ulonglong2*)(g_W2t + kp * 512 + c4 * 2 + 4);
#pragma unroll
        for (int r = 0; r < 8; r++) {
            ull x2 = *(const ull*)(xb + r * 512 + 2 * kp);
            FFMA2(acc[r][0], x2, wA.x);
            FFMA2(acc[r][1], x2, wA.y);
            FFMA2(acc[r][2], x2, wB.x);
            FFMA2(acc[r][3], x2, wB.y);
        }
    }

    float4 fw = *(const float4*)(fcW + c4);
    int lane = t & 31;
#pragma unroll
    for (int r = 0; r < 8; r++) {
        float v[4];
#pragma unroll
        for (int j = 0; j < 4; j++)
            v[j] = __uint_as_float((unsigned)acc[r][j])
                 + __uint_as_float((unsigned)(acc[r][j] >> 32));
        float sq = v[0]*v[0] + v[1]*v[1] + v[2]*v[2] + v[3]*v[3];
        float dt = v[0]*fw.x + v[1]*fw.y + v[2]*fw.z + v[3]*fw.w;
#pragma unroll
        for (int o = 16; o > 0; o >>= 1) {
            sq += __shfl_xor_sync(0xffffffffu, sq, o);
            dt += __shfl_xor_sync(0xffffffffu, dt, o);
        }
        if (lane == 0) {
            atomicAdd(&sSq[rg * 8 + r], sq);
            atomicAdd(&sDot[rg * 8 + r], dt);
        }
    }
    __syncthreads();
    if (t < 32) {
        float nrm = sqrtf(sSq[t]);
        out[r0 + t] = sDot[t] / fmaxf(nrm, 1e-12f) + fcb[0];
    }
}

// ---------------------------------------------------------------------------
extern "C" void kernel_launch(void* const* d_in, const int* in_sizes, int n_in,
                              void* d_out, int out_size) {
    const float* embedding = (const float*)d_in[0];
    const float* prep_W    = (const float*)d_in[1];
    const float* prep_b    = (const float*)d_in[2];
    const float* w1x       = (const float*)d_in[3];
    const float* w1n       = (const float*)d_in[4];
    const float* w2x       = (const float*)d_in[5];
    const float* w2n       = (const float*)d_in[6];
    const float* fcW       = (const float*)d_in[7];
    const float* fcb       = (const float*)d_in[8];
    const int*   ids       = (const int*)d_in[9];
    const int*   adj       = (const int*)d_in[10];
    const int*   perm1     = (const int*)d_in[11];
    const int*   perm2     = (const int*)d_in[12];
    const int n_nodes = in_sizes[0] / EMB - 1;

    // streams/events created once, on the (uncaptured) correctness call
    static cudaStream_t s1 = nullptr;
    static cudaEvent_t evG[NCHK], evF[NCHK];
    if (s1 == nullptr) {
        cudaStreamCreateWithFlags(&s1, cudaStreamNonBlocking);
        for (int c = 0; c < NCHK; c++) {
            cudaEventCreateWithFlags(&evG[c], cudaEventDisableTiming);
            cudaEventCreateWithFlags(&evF[c], cudaEventDisableTiming);
        }
    }

    const int smem_o = (32 * 512 + 64) * (int)sizeof(float);
    cudaFuncSetAttribute(final2, cudaFuncAttributeMaxDynamicSharedMemorySize, smem_o);

    prep_all<<<545, 256>>>(embedding, prep_W, prep_b, w1x, w1n, w2x, w2n, n_nodes);

    for (int c = 0; c < NCHK; c++) {
        gather_kernel<<<CHUNKB * NS / 8, 256>>>(embedding, ids, adj, perm1, perm2,
                                                c * CHUNKB * NS);
        cudaEventRecord(evG[c], 0);
        cudaStreamWaitEvent(s1, evG[c], 0);
        compute_mma<<<CGRID, 256, 0, s1>>>(c * CHUNKB);
        final2<<<CHUNKB / 32, 256, smem_o, s1>>>(fcW, fcb, (float*)d_out, c * CHUNKB);
        cudaEventRecord(evF[c], s1);
    }
    for (int c = 0; c < NCHK; c++) cudaStreamWaitEvent(0, evF[c], 0);
}

// round 17
// speedup vs baseline: 1.3511x; 1.3511x over previous
#include <cuda_runtime.h>
#include <cstdint>
#include <math.h>

#define EMB    64
#define NS     25
#define DEG    64
#define BATCH  4096
#define NSAMP  (BATCH * NS)
#define FR     68                     // shared feat row stride (conflict-free)
#define CGRID  296                    // persistent compute blocks (2/SM)

typedef unsigned long long ull;

// fma.rn.f32x2 — packed fp32 FMA (Blackwell). acc += a*b (two lanes)
#define FFMA2(acc, a, b) \
    asm("fma.rn.f32x2 %0, %1, %2, %3;" : "=l"(acc) : "l"(a), "l"(b), "l"(acc))

#define CVT_TF32(u, f) \
    asm("cvt.rna.tf32.f32 %0, %1;" : "=r"(u) : "f"(f))

#define MMA_TF32(c0, c1, c2, c3, a0, a1, a2, a3, b0, b1)                     \
    asm("mma.sync.aligned.m16n8k8.row.col.f32.tf32.tf32.f32 "                \
        "{%0,%1,%2,%3},{%4,%5,%6,%7},{%8,%9},{%0,%1,%2,%3};"                 \
        : "+f"(c0), "+f"(c1), "+f"(c2), "+f"(c3)                             \
        : "r"(a0), "r"(a1), "r"(a2), "r"(a3), "r"(b0), "r"(b1))

// ---------------- static device scratch (no allocation) --------------------
__device__ float g_Atc[256 * 64];             // folded layer-1 weights [c][k]
__device__ float g_bias1[256];                // [b1x ; b1n]
__device__ float g_x0[128];                   // feats0 @ w1x.T (pre-relu)
__device__ float g_W2t[512 * 256];            // layer-2 weights [128 kp][256 c][2]
__device__ float g_feats[(size_t)NSAMP * 128];// per sample: [e1(64)|mean2(64)]
__device__ float g_scr[(size_t)BATCH * 512];  // per batch: [h0cat(256)|h1mean(256)]

// ---------------------------------------------------------------------------
// prep_all: merged prep_A (blocks 0-31), prep_B (block 32), prep_W2 (33-544)
// ---------------------------------------------------------------------------
__global__ void __launch_bounds__(256)
prep_all(const float* __restrict__ emb,
         const float* __restrict__ prep_W,
         const float* __restrict__ prep_b,
         const float* __restrict__ w1x,
         const float* __restrict__ w1n,
         const float* __restrict__ w2x,
         const float* __restrict__ w2n,
         int n_nodes) {
    const int bid = blockIdx.x;
    const int t = threadIdx.x;

    if (bid < 32) {                   // ---- prep_A ----
        int idx = bid * 256 + t;      // 0..8191
        int k = idx >> 7, h = idx & 127;
        float ax = 0.f, an = 0.f;
#pragma unroll
        for (int c = 0; c < 64; c++) {
            float p = prep_W[c * 64 + k];
            ax += p * w1x[h * 64 + c];
            an += p * w1n[h * 64 + c];
        }
        g_Atc[h * 64 + k]         = ax;
        g_Atc[(128 + h) * 64 + k] = an;
    } else if (bid == 32) {           // ---- prep_B ----
        __shared__ float f0[64];
        if (t < 64) {
            const float* e = emb + (size_t)n_nodes * 64;
            float a = prep_b[t];
#pragma unroll
            for (int k = 0; k < 64; k++) a += e[k] * prep_W[t * 64 + k];
            f0[t] = a;
        }
        __syncthreads();
        if (t < 128) {
            float x0 = 0.f, bx = 0.f, bn = 0.f;
#pragma unroll
            for (int c = 0; c < 64; c++) {
                x0 += f0[c]     * w1x[t * 64 + c];
                bx += prep_b[c] * w1x[t * 64 + c];
                bn += prep_b[c] * w1n[t * 64 + c];
            }
            g_x0[t]          = x0;
            g_bias1[t]       = bx;
            g_bias1[128 + t] = bn;
        }
    } else {                          // ---- prep_W2 ----
        int idx = (bid - 33) * 256 + t;   // 0..131071
        int c = idx & 255, kk = idx >> 8;
        float v = (c < 128) ? w2x[c * 256 + kk] : w2n[(c - 128) * 256 + kk];
        g_W2t[(kk >> 1) * 512 + c * 2 + (kk & 1)] = v;
    }
}

// ---------------------------------------------------------------------------
// gather_kernel: 1 warp = 1 sample (HBM-roofline proven: ~87us, DRAM 80%).
// ---------------------------------------------------------------------------
__global__ void __launch_bounds__(256)
gather_kernel(const float* __restrict__ emb,
              const int* __restrict__ ids,
              const int* __restrict__ adj,
              const int* __restrict__ perm1,
              const int* __restrict__ perm2) {
    int t = threadIdx.x;
    int w = t >> 5, lane = t & 31;
    int s = blockIdx.x * 8 + w;                  // sample index
    int i = s / NS;
    int j = s - i * NS;

    int id0 = __ldg(&ids[i]);
    int p1  = __ldg(&perm1[j]);
    int id1 = __ldg(&adj[(size_t)id0 * DEG + p1]);

    int p2  = __ldg(&perm2[lane < NS ? lane : 0]);
    int nb  = __ldg(&adj[(size_t)id1 * DEG + p2]);

    float2 e1 = *(const float2*)(emb + (size_t)id1 * 64 + 2 * lane);

    float sx = 0.f, sy = 0.f;
#pragma unroll
    for (int k = 0; k < NS; k++) {
        int idk = __shfl_sync(0xffffffffu, nb, k);
        float2 v = *(const float2*)(emb + (size_t)idk * 64 + 2 * lane);
        sx += v.x; sy += v.y;
    }
    const float inv25 = 1.0f / 25.0f;
    float* dst = g_feats + (size_t)s * 128;
    *(float2*)(dst + 2 * lane)      = e1;
    *(float2*)(dst + 64 + 2 * lane) = make_float2(sx * inv25, sy * inv25);
}

// ---------------------------------------------------------------------------
// compute_mma: persistent tf32 mma.sync compute (PROVEN round-15, 186.9us
// config). 296 blocks (2/SM), grid-stride, cp.async double-buffered staging.
// ---------------------------------------------------------------------------
__device__ __forceinline__ void cp16(unsigned int saddr, const void* g) {
    asm volatile("cp.async.cg.shared.global [%0], [%1], 16;" :: "r"(saddr), "l"(g));
}

__global__ void __launch_bounds__(256, 2)
compute_mma() {
    __shared__ float Fbuf[2][2][32 * FR];     // [buf][x/n][rows]

    const int t = threadIdx.x;
    const int w = t >> 5, lane = t & 31;
    const int g = lane >> 2, t4 = lane & 3;
    const int wcol = w * 32;                  // global output col base
    const bool isN = (w >= 4);
    const float inv25 = 1.0f / 25.0f;

    // ---- load B fragments (weights) once: b[n8][k8][2] ----
    unsigned bfr[4][8][2];
#pragma unroll
    for (int n8 = 0; n8 < 4; n8++) {
        int c = wcol + n8 * 8 + g;
#pragma unroll
        for (int k8 = 0; k8 < 8; k8++) {
            float v0 = g_Atc[c * 64 + k8 * 8 + t4];
            float v1 = g_Atc[c * 64 + k8 * 8 + t4 + 4];
            CVT_TF32(bfr[n8][k8][0], v0);
            CVT_TF32(bfr[n8][k8][1], v1);
        }
    }
    float biasE[4], biasO[4];
#pragma unroll
    for (int n8 = 0; n8 < 4; n8++) {
        biasE[n8] = g_bias1[wcol + n8 * 8 + 2 * t4];
        biasO[n8] = g_bias1[wcol + n8 * 8 + 2 * t4 + 1];
    }
    const float x0v = (t < 128) ? g_x0[t] : 0.f;

#define STAGE(i_, b_)                                                         \
    do {                                                                      \
        const float4* src_ = (const float4*)(g_feats + (size_t)(i_) * NS * 128); \
        unsigned bx_ = (unsigned)__cvta_generic_to_shared(&Fbuf[b_][0][0]);   \
        unsigned bn_ = (unsigned)__cvta_generic_to_shared(&Fbuf[b_][1][0]);   \
        _Pragma("unroll")                                                     \
        for (int idx = t; idx < 400; idx += 256) {                            \
            int s_ = idx >> 4, q_ = idx & 15;                                 \
            cp16(bx_ + (s_ * FR + q_ * 4) * 4, src_ + s_ * 32 + q_);          \
            cp16(bn_ + (s_ * FR + q_ * 4) * 4, src_ + s_ * 32 + 16 + q_);     \
        }                                                                     \
        asm volatile("cp.async.commit_group;" ::: "memory");                  \
    } while (0)

    int i = blockIdx.x;
    if (i < BATCH) STAGE(i, 0);
    int buf = 0;

    for (; i < BATCH; i += CGRID) {
        const int nxt = i + CGRID;
        if (nxt < BATCH) {
            STAGE(nxt, buf ^ 1);
            asm volatile("cp.async.wait_group 1;" ::: "memory");
        } else {
            asm volatile("cp.async.wait_group 0;" ::: "memory");
        }
        __syncthreads();              // current buffer fully staged

        float* Fx = &Fbuf[buf][0][0];
        float* Fn = &Fbuf[buf][1][0];
        if (t < 64) {                 // mean1 -> Fn row 25
            float m = 0.f;
#pragma unroll
            for (int s = 0; s < NS; s++) m += Fx[s * FR + t];
            Fn[25 * FR + t] = m * inv25;
        }
        __syncthreads();

        const float* Fw = isN ? Fn : Fx;

        // ---- mma ----
        float cfr[2][4][4];
#pragma unroll
        for (int m = 0; m < 2; m++)
#pragma unroll
            for (int n8 = 0; n8 < 4; n8++)
#pragma unroll
                for (int q = 0; q < 4; q++) cfr[m][n8][q] = 0.f;

#pragma unroll
        for (int m = 0; m < 2; m++) {
            int rb = m * 16;
#pragma unroll
            for (int k8 = 0; k8 < 8; k8++) {
                unsigned a0, a1, a2, a3;
                CVT_TF32(a0, Fw[(rb + g) * FR + k8 * 8 + t4]);
                CVT_TF32(a1, Fw[(rb + g + 8) * FR + k8 * 8 + t4]);
                CVT_TF32(a2, Fw[(rb + g) * FR + k8 * 8 + t4 + 4]);
                CVT_TF32(a3, Fw[(rb + g + 8) * FR + k8 * 8 + t4 + 4]);
#pragma unroll
                for (int n8 = 0; n8 < 4; n8++)
                    MMA_TF32(cfr[m][n8][0], cfr[m][n8][1], cfr[m][n8][2], cfr[m][n8][3],
                             a0, a1, a2, a3, bfr[n8][k8][0], bfr[n8][k8][1]);
            }
        }

        // ---- epilogue ----
        float* scr = g_scr + (size_t)i * 512;
        if (t < 128) scr[t] = fmaxf(x0v, 0.f);     // h0 x-part
#pragma unroll
        for (int n8 = 0; n8 < 4; n8++) {
            float vE = fmaxf(cfr[0][n8][0] + biasE[n8], 0.f)
                     + fmaxf(cfr[0][n8][2] + biasE[n8], 0.f)
                     + fmaxf(cfr[1][n8][0] + biasE[n8], 0.f);
            float vO = fmaxf(cfr[0][n8][1] + biasO[n8], 0.f)
                     + fmaxf(cfr[0][n8][3] + biasO[n8], 0.f)
                     + fmaxf(cfr[1][n8][1] + biasO[n8], 0.f);
            if (g == 0) {
                vE += fmaxf(cfr[1][n8][2] + biasE[n8], 0.f);
                vO += fmaxf(cfr[1][n8][3] + biasO[n8], 0.f);
            }
            if (isN && g == 1) {       // row 25 = mean1 @ A1n -> h0 n-part
                scr[wcol + n8 * 8 + 2 * t4]     = fmaxf(cfr[1][n8][2] + biasE[n8], 0.f);
                scr[wcol + n8 * 8 + 2 * t4 + 1] = fmaxf(cfr[1][n8][3] + biasO[n8], 0.f);
            }
#pragma unroll
            for (int o = 4; o < 32; o <<= 1) {
                vE += __shfl_xor_sync(0xffffffffu, vE, o);
                vO += __shfl_xor_sync(0xffffffffu, vO, o);
            }
            if (lane < 4) {
                scr[256 + wcol + n8 * 8 + 2 * lane]     = vE * inv25;
                scr[256 + wcol + n8 * 8 + 2 * lane + 1] = vO * inv25;
            }
        }
        __syncthreads();              // everyone done with buf before refill
        buf ^= 1;
    }
#undef STAGE
}

// ---------------------------------------------------------------------------
// final3: layer-2 GEMM, 16 rows/block (grid 256, ~2 blocks/SM) for latency
// hiding. Thread = 4 cols x 4 rows; then L2-normalize + fc.
// ---------------------------------------------------------------------------
__global__ void __launch_bounds__(256)
final3(const float* __restrict__ fcW,
       const float* __restrict__ fcb,
       float* __restrict__ out) {
    extern __shared__ float fsm[];
    float* in_sh = fsm;                 // 16 x 512
    float* sSq   = fsm + 16 * 512;
    float* sDot  = sSq + 16;

    int t  = threadIdx.x;
    int r0 = blockIdx.x * 16;

    {
        const float4* src = (const float4*)(g_scr + (size_t)r0 * 512);
        float4* dst = (float4*)in_sh;
#pragma unroll
        for (int q = 0; q < 8; q++) dst[t + q * 256] = src[t + q * 256];
    }
    if (t < 16) { sSq[t] = 0.f; sDot[t] = 0.f; }
    __syncthreads();

    const int c4 = (t & 63) * 4;            // 4 output cols
    const int rg = t >> 6;                  // row group (4 rows)
    const int ioff = (c4 < 128) ? 0 : 256;
    const float* xb = in_sh + rg * 4 * 512 + ioff;

    ull acc[4][4];
#pragma unroll
    for (int r = 0; r < 4; r++)
#pragma unroll
        for (int j = 0; j < 4; j++) acc[r][j] = 0ull;

#pragma unroll 8
    for (int kp = 0; kp < 128; kp++) {
        ulonglong2 wA = *(const ulonglong2*)(g_W2t + kp * 512 + c4 * 2);
        ulonglong2 wB = *(const ulonglong2*)(g_W2t + kp * 512 + c4 * 2 + 4);
#pragma unroll
        for (int r = 0; r < 4; r++) {
            ull x2 = *(const ull*)(xb + r * 512 + 2 * kp);
            FFMA2(acc[r][0], x2, wA.x);
            FFMA2(acc[r][1], x2, wA.y);
            FFMA2(acc[r][2], x2, wB.x);
            FFMA2(acc[r][3], x2, wB.y);
        }
    }

    float4 fw = *(const float4*)(fcW + c4);
    int lane = t & 31;
#pragma unroll
    for (int r = 0; r < 4; r++) {
        int row = rg * 4 + r;
        float v[4];
#pragma unroll
        for (int j = 0; j < 4; j++)
            v[j] = __uint_as_float((unsigned)acc[r][j])
                 + __uint_as_float((unsigned)(acc[r][j] >> 32));
        float sq = v[0]*v[0] + v[1]*v[1] + v[2]*v[2] + v[3]*v[3];
        float dt = v[0]*fw.x + v[1]*fw.y + v[2]*fw.z + v[3]*fw.w;
#pragma unroll
        for (int o = 16; o > 0; o >>= 1) {
            sq += __shfl_xor_sync(0xffffffffu, sq, o);
            dt += __shfl_xor_sync(0xffffffffu, dt, o);
        }
        if (lane == 0) {
            atomicAdd(&sSq[row], sq);
            atomicAdd(&sDot[row], dt);
        }
    }
    __syncthreads();
    if (t < 16) {
        float nrm = sqrtf(sSq[t]);
        out[r0 + t] = sDot[t] / fmaxf(nrm, 1e-12f) + fcb[0];
    }
}

// ---------------------------------------------------------------------------
extern "C" void kernel_launch(void* const* d_in, const int* in_sizes, int n_in,
                              void* d_out, int out_size) {
    const float* embedding = (const float*)d_in[0];
    const float* prep_W    = (const float*)d_in[1];
    const float* prep_b    = (const float*)d_in[2];
    const float* w1x       = (const float*)d_in[3];
    const float* w1n       = (const float*)d_in[4];
    const float* w2x       = (const float*)d_in[5];
    const float* w2n       = (const float*)d_in[6];
    const float* fcW       = (const float*)d_in[7];
    const float* fcb       = (const float*)d_in[8];
    const int*   ids       = (const int*)d_in[9];
    const int*   adj       = (const int*)d_in[10];
    const int*   perm1     = (const int*)d_in[11];
    const int*   perm2     = (const int*)d_in[12];
    const int n_nodes = in_sizes[0] / EMB - 1;

    prep_all<<<545, 256>>>(embedding, prep_W, prep_b, w1x, w1n, w2x, w2n, n_nodes);

    gather_kernel<<<NSAMP / 8, 256>>>(embedding, ids, adj, perm1, perm2);

    compute_mma<<<CGRID, 256>>>();

    const int smem_o = (16 * 512 + 64) * (int)sizeof(float);
    cudaFuncSetAttribute(final3, cudaFuncAttributeMaxDynamicSharedMemorySize, smem_o);
    final3<<<BATCH / 16, 256, smem_o>>>(fcW, fcb, (float*)d_out);
}